// round 11
// baseline (speedup 1.0000x reference)
#include <cuda_runtime.h>

// Problem constants
#define BATCH 4
#define T 32
#define NTOK (BATCH * T)      // 128
#define C 512
#define ENC 32
#define DIM 1024

// Scratch (no allocations allowed): device globals
__device__ float  d_Qx[NTOK][4][32];   // SoA Q real  ([b*32+j][k][r])
__device__ float  d_Qy[NTOK][4][32];   // SoA Q imag
__device__ float2 d_P[NTOK][4][32];    // AoS (fallback path only)
__device__ float2 d_Q[NTOK][4][32];    // AoS (fallback path only)
__device__ unsigned d_ctr   = 0;       // barrier arrivals (self-resetting)
__device__ unsigned d_epoch = 0;       // barrier epoch (monotonic across replays)

__device__ __forceinline__ float2 cmul(float2 a, float2 b) {
    return make_float2(a.x * b.x - a.y * b.y, a.x * b.y + a.y * b.x);
}

// packed f32x2 helpers (sm_103a)
__device__ __forceinline__ unsigned long long pack2(float lo, float hi) {
    unsigned long long r;
    asm("mov.b64 %0, {%1, %2};" : "=l"(r) : "f"(lo), "f"(hi));
    return r;
}
__device__ __forceinline__ void unpack2(unsigned long long v, float& lo, float& hi) {
    asm("mov.b64 {%0, %1}, %2;" : "=f"(lo), "=f"(hi) : "l"(v));
}
__device__ __forceinline__ unsigned long long fma2(unsigned long long a,
                                                   unsigned long long b,
                                                   unsigned long long c) {
    unsigned long long d;
    asm("fma.rn.f32x2 %0, %1, %2, %3;" : "=l"(d) : "l"(a), "l"(b), "l"(c));
    return d;
}

// ---------------------------------------------------------------------------
// FUSED persistent kernel (live path, real-part output).
// grid = 128 (block per token (b,i)), block = 512. All blocks co-resident
// (1 block/SM on 148 SMs), so the device-wide fence+flag barrier is safe.
//
// Phase A (enc): enc = normalize(x@W^T + b); u = Ga*enc, v = Gb*enc;
//   P_k[r] = sum_{m:m&1==pa} G2a[r][m^fa] * u[m ^ (m>>1)]     (kept in smem)
//   Q_k[r] = sum_{m:m&1==pb} G2b[r][m]  * v[(m ^ (m>>1)) ^ xb] (to global SoA)
//   (Ga = kron(RY0*RX0) wires 0..4, Gb wires 5..9, G2 = kron(RY1);
//    sigma_inv(m)=m^(m>>1); pa=k>>1, fa=(k&1)<<4, pb=k&1, xb=(k>>1)<<4)
// Barrier: fence + atomic arrivals + epoch flip (replay-safe, self-resetting).
// Phase B (expand): stage batch-b Q into smem SoA, P packed into regs;
//   thread = 4a x 4b0 patch for j = jo*8+lane; per j: 8 LDS.128, 32 fma2,
//   4 STG.128.  out[(tok*32 + j)*1024 + a*32 + b0] = sum_k Px*Qx - Py*Qy.
// ---------------------------------------------------------------------------
__global__ void __launch_bounds__(512)
fused_kernel(const float* __restrict__ x,
             const float* __restrict__ W,
             const float* __restrict__ bias,
             const float* __restrict__ th_rx0,
             const float* __restrict__ th_ry0,
             const float* __restrict__ th_ry1,
             float* __restrict__ out) {
    __shared__ union Shm {
        struct {
            float2 Ga[32][32], Gb[32][32];
            float  G2a[32][32], G2b[32][32];
        } A;
        struct {
            float Qx[32][4][32];   // [j][k][b0]
            float Qy[32][4][32];
        } B;
    } sh;
    __shared__ float2 M1w[10][2][2];
    __shared__ float  M2w[10][2][2];
    __shared__ float  partial[16][32];
    __shared__ float  e[32];
    __shared__ float2 us[32], vs[32];
    __shared__ float2 Psm[4][32];

    int tok = blockIdx.x;          // b*32 + i
    int b   = tok >> 5;
    int tid = threadIdx.x;         // 512

    // ---- Phase A: encoder + P/Q ----
    if (tid < 10) {
        float crx = cosf(th_rx0[tid] * 0.5f), srx = sinf(th_rx0[tid] * 0.5f);
        float cry = cosf(th_ry0[tid] * 0.5f), sry = sinf(th_ry0[tid] * 0.5f);
        M1w[tid][0][0] = make_float2( cry * crx,  sry * srx);
        M1w[tid][0][1] = make_float2(-sry * crx, -cry * srx);
        M1w[tid][1][0] = make_float2( sry * crx, -cry * srx);
        M1w[tid][1][1] = make_float2( cry * crx, -sry * srx);
        float c1 = cosf(th_ry1[tid] * 0.5f), s1 = sinf(th_ry1[tid] * 0.5f);
        M2w[tid][0][0] =  c1; M2w[tid][0][1] = -s1;
        M2w[tid][1][0] =  s1; M2w[tid][1][1] =  c1;
    }
    __syncthreads();

    // Kronecker factors (2 cells per thread)
    for (int cell = tid; cell < 1024; cell += 512) {
        int r = cell >> 5, c = cell & 31;
        float2 ga = make_float2(1.f, 0.f), gb = make_float2(1.f, 0.f);
        float g2a = 1.f, g2b = 1.f;
#pragma unroll
        for (int j = 0; j < 5; j++) {
            int rb = (r >> (4 - j)) & 1;
            int cb = (c >> (4 - j)) & 1;
            ga  = cmul(ga, M1w[j][rb][cb]);
            gb  = cmul(gb, M1w[5 + j][rb][cb]);
            g2a *= M2w[j][rb][cb];
            g2b *= M2w[5 + j][rb][cb];
        }
        sh.A.Ga[r][c] = ga; sh.A.Gb[r][c] = gb;
        sh.A.G2a[r][c] = g2a; sh.A.G2b[r][c] = g2b;
    }

    // GEMV: thread (p,k) sums 32 c-elements (8 float4) of W row k
    {
        int k = tid & 31, p = tid >> 5;   // p 0..15
        const float4* wr4 = (const float4*)(W + (size_t)k * C + p * 32);
        const float4* xc4 = (const float4*)(x + (size_t)tok * C + p * 32);
        float s = 0.f;
#pragma unroll
        for (int cc = 0; cc < 8; cc++) {
            float4 wv = wr4[cc];
            float4 xv = xc4[cc];
            s += wv.x * xv.x + wv.y * xv.y + wv.z * xv.z + wv.w * xv.w;
        }
        partial[p][k] = s;
    }
    __syncthreads();

    if (tid < 32) {
        float v = bias[tid];
#pragma unroll
        for (int p = 0; p < 16; p++) v += partial[p][tid];
        float sq = v * v;
#pragma unroll
        for (int o = 16; o; o >>= 1) sq += __shfl_xor_sync(0xffffffffu, sq, o);
        e[tid] = v * rsqrtf(sq);
    }
    __syncthreads();

    // u = Ga * e, v = Gb * e
    if (tid < 64) {
        int r = tid & 31, side = tid >> 5;
        float re = 0.f, im = 0.f;
#pragma unroll
        for (int c = 0; c < 32; c++) {
            float ev = e[c];
            float2 m = side ? sh.A.Gb[r][c] : sh.A.Ga[r][c];
            re += m.x * ev; im += m.y * ev;
        }
        if (side) vs[r] = make_float2(re, im);
        else      us[r] = make_float2(re, im);
    }
    __syncthreads();

    // P (to smem) and Q (to global SoA): 256 outputs, threads 0..255
    if (tid < 256) {
        int which = tid >> 7;           // 0 -> P, 1 -> Q
        int k4 = (tid >> 5) & 3;
        int rr = tid & 31;
        float re = 0.f, im = 0.f;
        if (which == 0) {
            int pa = k4 >> 1, fa = (k4 & 1) << 4;
#pragma unroll
            for (int mm = 0; mm < 16; mm++) {
                int m = (mm << 1) | pa;
                float2 uu = us[m ^ (m >> 1)];
                float g = sh.A.G2a[rr][m ^ fa];
                re += g * uu.x; im += g * uu.y;
            }
            Psm[k4][rr] = make_float2(re, im);
        } else {
            int pb = k4 & 1, xb = (k4 >> 1) << 4;
#pragma unroll
            for (int mm = 0; mm < 16; mm++) {
                int m = (mm << 1) | pb;
                float2 vv = vs[(m ^ (m >> 1)) ^ xb];
                float g = sh.A.G2b[rr][m];
                re += g * vv.x; im += g * vv.y;
            }
            d_Qx[tok][k4][rr] = re;
            d_Qy[tok][k4][rr] = im;
        }
    }
    __threadfence();
    __syncthreads();

    // ---- Device-wide barrier (fence + flag; epoch-based, replay-safe) ----
    if (tid == 0) {
        unsigned e0 = *(volatile unsigned*)&d_epoch;
        unsigned t = atomicAdd(&d_ctr, 1u);
        if (t == (unsigned)gridDim.x - 1u) {
            d_ctr = 0;
            __threadfence();
            atomicAdd(&d_epoch, 1u);
        }
        while (*(volatile unsigned*)&d_epoch == e0) { }
        __threadfence();
    }
    __syncthreads();

    // ---- Phase B: expand ----
    // Stage all Q of batch b into smem SoA (contiguous: [b*32..b*32+31])
    {
        const float4* gx = (const float4*)&d_Qx[b << 5][0][0];   // 1024 float4
        const float4* gy = (const float4*)&d_Qy[b << 5][0][0];
        float4* sx = (float4*)&sh.B.Qx[0][0][0];
        float4* sy = (float4*)&sh.B.Qy[0][0][0];
#pragma unroll
        for (int n = 0; n < 2; n++) {
            int idx = tid + n * 512;
            sx[idx] = gx[idx];
            sy[idx] = gy[idx];
        }
    }

    int lane = tid >> 6;            // 0..7 (j-lane)
    int t4 = tid & 63;
    int a_base = (t4 >> 3) << 2;    // 0,4,...,28
    int b0 = (t4 & 7) << 2;         // 0,4,...,28

    // P pre-packed pairs from smem (reads Psm, disjoint from sh.B)
    unsigned long long pxx[4][4], pyn[4][4];
#pragma unroll
    for (int k = 0; k < 4; k++)
#pragma unroll
        for (int da = 0; da < 4; da++) {
            float2 Pv = Psm[k][a_base + da];
            pxx[da][k] = pack2(Pv.x, Pv.x);
            pyn[da][k] = pack2(-Pv.y, -Pv.y);
        }
    __syncthreads();

    float* obase = out + ((size_t)tok << 15);   // tok*32*1024
#pragma unroll
    for (int jo = 0; jo < 4; jo++) {
        int j = (jo << 3) | lane;
        unsigned long long qxL[4], qxH[4], qyL[4], qyH[4];
#pragma unroll
        for (int k = 0; k < 4; k++) {
            float4 fx = *(const float4*)&sh.B.Qx[j][k][b0];
            qxL[k] = pack2(fx.x, fx.y); qxH[k] = pack2(fx.z, fx.w);
            float4 fy = *(const float4*)&sh.B.Qy[j][k][b0];
            qyL[k] = pack2(fy.x, fy.y); qyH[k] = pack2(fy.z, fy.w);
        }
        float* oj = obase + ((size_t)j << 10);
#pragma unroll
        for (int da = 0; da < 4; da++) {
            unsigned long long accL = 0ull, accH = 0ull;   // (0.0f,0.0f)
#pragma unroll
            for (int k = 0; k < 4; k++) {
                accL = fma2(pxx[da][k], qxL[k], accL);
                accL = fma2(pyn[da][k], qyL[k], accL);
                accH = fma2(pxx[da][k], qxH[k], accH);
                accH = fma2(pyn[da][k], qyH[k], accH);
            }
            float r0, r1, r2, r3;
            unpack2(accL, r0, r1);
            unpack2(accH, r2, r3);
            *(float4*)&oj[(a_base + da) * 32 + b0] = make_float4(r0, r1, r2, r3);
        }
    }
}

// ---------------------------------------------------------------------------
// Fallback path (out_size != 4194304): two-kernel interleaved-complex pipeline.
// ---------------------------------------------------------------------------
__global__ void __launch_bounds__(256)
enc_pq_kernel(const float* __restrict__ x,
              const float* __restrict__ W,
              const float* __restrict__ bias,
              const float* __restrict__ th_rx0,
              const float* __restrict__ th_ry0,
              const float* __restrict__ th_ry1) {
    __shared__ float2 M1w[10][2][2];
    __shared__ float  M2w[10][2][2];
    __shared__ float2 Ga[32][32], Gb[32][32];
    __shared__ float  G2a[32][32], G2b[32][32];
    __shared__ float  partial[8][32];
    __shared__ float  e[32];
    __shared__ float2 us[32], vs[32];

    int tok = blockIdx.x;
    int tid = threadIdx.x;  // 256

    if (tid < 10) {
        float crx = cosf(th_rx0[tid] * 0.5f), srx = sinf(th_rx0[tid] * 0.5f);
        float cry = cosf(th_ry0[tid] * 0.5f), sry = sinf(th_ry0[tid] * 0.5f);
        M1w[tid][0][0] = make_float2( cry * crx,  sry * srx);
        M1w[tid][0][1] = make_float2(-sry * crx, -cry * srx);
        M1w[tid][1][0] = make_float2( sry * crx, -cry * srx);
        M1w[tid][1][1] = make_float2( cry * crx, -sry * srx);
        float c1 = cosf(th_ry1[tid] * 0.5f), s1 = sinf(th_ry1[tid] * 0.5f);
        M2w[tid][0][0] =  c1; M2w[tid][0][1] = -s1;
        M2w[tid][1][0] =  s1; M2w[tid][1][1] =  c1;
    }
    __syncthreads();

    for (int cell = tid; cell < 1024; cell += 256) {
        int r = cell >> 5, c = cell & 31;
        float2 ga = make_float2(1.f, 0.f), gb = make_float2(1.f, 0.f);
        float g2a = 1.f, g2b = 1.f;
#pragma unroll
        for (int j = 0; j < 5; j++) {
            int rb = (r >> (4 - j)) & 1;
            int cb = (c >> (4 - j)) & 1;
            ga  = cmul(ga, M1w[j][rb][cb]);
            gb  = cmul(gb, M1w[5 + j][rb][cb]);
            g2a *= M2w[j][rb][cb];
            g2b *= M2w[5 + j][rb][cb];
        }
        Ga[r][c] = ga; Gb[r][c] = gb; G2a[r][c] = g2a; G2b[r][c] = g2b;
    }

    {
        int k = tid & 31, p = tid >> 5;
        const float4* wr4 = (const float4*)(W + (size_t)k * C + p * 64);
        const float4* xc4 = (const float4*)(x + (size_t)tok * C + p * 64);
        float s = 0.f;
#pragma unroll
        for (int cc = 0; cc < 16; cc++) {
            float4 wv = wr4[cc];
            float4 xv = xc4[cc];
            s += wv.x * xv.x + wv.y * xv.y + wv.z * xv.z + wv.w * xv.w;
        }
        partial[p][k] = s;
    }
    __syncthreads();

    if (tid < 32) {
        float v = bias[tid];
#pragma unroll
        for (int p = 0; p < 8; p++) v += partial[p][tid];
        float sq = v * v;
#pragma unroll
        for (int o = 16; o; o >>= 1) sq += __shfl_xor_sync(0xffffffffu, sq, o);
        e[tid] = v * rsqrtf(sq);
    }
    __syncthreads();

    if (tid < 64) {
        int r = tid & 31, side = tid >> 5;
        float re = 0.f, im = 0.f;
#pragma unroll
        for (int c = 0; c < 32; c++) {
            float ev = e[c];
            float2 m = side ? Gb[r][c] : Ga[r][c];
            re += m.x * ev; im += m.y * ev;
        }
        if (side) vs[r] = make_float2(re, im);
        else      us[r] = make_float2(re, im);
    }
    __syncthreads();

    {
        int o = tid;
        int which = o >> 7;
        int k4 = (o >> 5) & 3;
        int rr = o & 31;
        float re = 0.f, im = 0.f;
        if (which == 0) {
            int pa = k4 >> 1, fa = (k4 & 1) << 4;
#pragma unroll
            for (int mm = 0; mm < 16; mm++) {
                int m = (mm << 1) | pa;
                float2 uu = us[m ^ (m >> 1)];
                float g = G2a[rr][m ^ fa];
                re += g * uu.x; im += g * uu.y;
            }
            d_P[tok][k4][rr] = make_float2(re, im);
        } else {
            int pb = k4 & 1, xb = (k4 >> 1) << 4;
#pragma unroll
            for (int mm = 0; mm < 16; mm++) {
                int m = (mm << 1) | pb;
                float2 vv = vs[(m ^ (m >> 1)) ^ xb];
                float g = G2b[rr][m];
                re += g * vv.x; im += g * vv.y;
            }
            d_Q[tok][k4][rr] = make_float2(re, im);
        }
    }
}

__global__ void __launch_bounds__(512)
expand_cplx_kernel(float4* __restrict__ out, long long nf4_limit) {
    int blk = blockIdx.x;          // b*1024 + i*32 + j
    int b = blk >> 10;
    int i = (blk >> 5) & 31;
    int j = blk & 31;

    __shared__ float2 Ps[4][32];
    __shared__ float2 Qs[4][32];

    int tid = threadIdx.x;  // 512
    if (tid < 128) {
        Ps[tid >> 5][tid & 31] = d_P[b * T + i][tid >> 5][tid & 31];
    } else if (tid < 256) {
        int t = tid - 128;
        Qs[t >> 5][t & 31] = d_Q[b * T + j][t >> 5][t & 31];
    }
    __syncthreads();

    int e0 = tid * 2;
    int a  = e0 >> 5;
    int b0 = e0 & 31;

    unsigned long long acc0 = 0ull, acc1 = 0ull;
#pragma unroll
    for (int k = 0; k < 4; k++) {
        float2 P  = Ps[k][a];
        float2 Q0 = Qs[k][b0];
        float2 Q1 = Qs[k][b0 + 1];
        unsigned long long pxx = pack2(P.x, P.x);
        unsigned long long pyn = pack2(-P.y, P.y);
        acc0 = fma2(pxx, pack2(Q0.x, Q0.y), acc0);
        acc0 = fma2(pyn, pack2(Q0.y, Q0.x), acc0);
        acc1 = fma2(pxx, pack2(Q1.x, Q1.y), acc1);
        acc1 = fma2(pyn, pack2(Q1.y, Q1.x), acc1);
    }
    float re0, im0, re1, im1;
    unpack2(acc0, re0, im0);
    unpack2(acc1, re1, im1);

    long long idx = (long long)blk * 512 + tid;
    if (idx < nf4_limit)
        out[idx] = make_float4(re0, im0, re1, im1);
}

// ---------------------------------------------------------------------------
extern "C" void kernel_launch(void* const* d_in, const int* in_sizes, int n_in,
                              void* d_out, int out_size) {
    // Resolve inputs by element count (order-independent):
    //   x: 65536 (B*T*C), W_tok: 16384 (ENC*C), b_tok: 32 (ENC),
    //   thetas: three size-10 arrays, relative order rx0, ry0, ry1.
    const float* x = nullptr;
    const float* W = nullptr;
    const float* bvec = nullptr;
    const float* th[3] = {nullptr, nullptr, nullptr};
    int nth = 0;
    for (int i = 0; i < n_in; i++) {
        int sz = in_sizes[i];
        const float* p = (const float*)d_in[i];
        if (sz == BATCH * T * C)      x = p;
        else if (sz == ENC * C)       W = p;
        else if (sz == ENC)           bvec = p;
        else if (sz == 10 && nth < 3) th[nth++] = p;
    }
    if (!x || !W || !bvec || nth != 3) return;

    if (out_size == 4194304) {
        // Live path: single fused persistent kernel (real-part output).
        fused_kernel<<<NTOK, 512>>>(x, W, bvec, th[0], th[1], th[2],
                                    (float*)d_out);
    } else {
        // Fallback: interleaved complex pairs, two-kernel pipeline.
        enc_pq_kernel<<<NTOK, 256>>>(x, W, bvec, th[0], th[1], th[2]);
        long long nfloats = (long long)out_size;
        if (nfloats > 8388608LL) nfloats = 8388608LL;
        long long nf4 = nfloats / 4;
        if (nf4 > 2097152LL) nf4 = 2097152LL;
        expand_cplx_kernel<<<BATCH * T * T, 512>>>((float4*)d_out, nf4);
    }
}

// round 13
// speedup vs baseline: 1.1033x; 1.1033x over previous
#include <cuda_runtime.h>

// Problem constants
#define BATCH 4
#define T 32
#define NTOK (BATCH * T)      // 128
#define C 512
#define ENC 32
#define DIM 1024

// Scratch (no allocations allowed): device globals
__device__ float  d_Qx[NTOK][4][32];   // SoA Q real   ([b*32+j][k][r])
__device__ float  d_Qy[NTOK][4][32];   // SoA Q imag
__device__ float2 d_Pxx[NTOK][4][32];  // ( P.x,  P.x) packed pairs
__device__ float2 d_Pyn[NTOK][4][32];  // (-P.y, -P.y) packed pairs
__device__ float2 d_P[NTOK][4][32];    // AoS (fallback path only)
__device__ float2 d_Q[NTOK][4][32];    // AoS (fallback path only)

__device__ __forceinline__ float2 cmul(float2 a, float2 b) {
    return make_float2(a.x * b.x - a.y * b.y, a.x * b.y + a.y * b.x);
}

// packed f32x2 helpers (sm_103a)
__device__ __forceinline__ unsigned long long pack2(float lo, float hi) {
    unsigned long long r;
    asm("mov.b64 %0, {%1, %2};" : "=l"(r) : "f"(lo), "f"(hi));
    return r;
}
__device__ __forceinline__ void unpack2(unsigned long long v, float& lo, float& hi) {
    asm("mov.b64 {%0, %1}, %2;" : "=f"(lo), "=f"(hi) : "l"(v));
}
__device__ __forceinline__ unsigned long long fma2(unsigned long long a,
                                                   unsigned long long b,
                                                   unsigned long long c) {
    unsigned long long d;
    asm("fma.rn.f32x2 %0, %1, %2, %3;" : "=l"(d) : "l"(a), "l"(b), "l"(c));
    return d;
}

// ---------------------------------------------------------------------------
// Kernel 1: per token (grid=128, block=512):
//   enc = normalize(x@W^T + b); u = Ga*enc, v = Gb*enc;
//   P_k[r] = sum_{m:m&1==pa} G2a[r][m^fa] * u[m ^ (m>>1)]
//   Q_k[r] = sum_{m:m&1==pb} G2b[r][m]  * v[(m ^ (m>>1)) ^ xb]
//   (Ga = kron(RY0*RX0) wires 0..4, Gb wires 5..9, G2 = kron(RY1);
//    sigma_inv(m)=m^(m>>1); pa=k>>1, fa=(k&1)<<4, pb=k&1, xb=(k>>1)<<4)
// GEMV global loads are issued at kernel entry so their DRAM latency
// overlaps the trig + Kronecker-build compute.
// Emits SoA Qx/Qy and pre-packed Pxx/Pyn for the expand kernel.
// ---------------------------------------------------------------------------
__global__ void __launch_bounds__(512)
enc_pq_kernel(const float* __restrict__ x,
              const float* __restrict__ W,
              const float* __restrict__ bias,
              const float* __restrict__ th_rx0,
              const float* __restrict__ th_ry0,
              const float* __restrict__ th_ry1) {
    __shared__ float2 M1w[10][2][2];
    __shared__ float  M2w[10][2][2];
    __shared__ float2 Ga[32][32], Gb[32][32];
    __shared__ float  G2a[32][32], G2b[32][32];
    __shared__ float  partial[16][32];
    __shared__ float  e[32];
    __shared__ float2 us[32], vs[32];

    int tok = blockIdx.x;
    int tid = threadIdx.x;  // 512

    // --- Issue GEMV loads FIRST (latency overlapped with trig/Kron) ---
    int gk = tid & 31, gp = tid >> 5;   // gp 0..15, 32 floats each
    float4 wv[8], xv[8];
    {
        const float4* wr4 = (const float4*)(W + (size_t)gk * C + gp * 32);
        const float4* xc4 = (const float4*)(x + (size_t)tok * C + gp * 32);
#pragma unroll
        for (int cc = 0; cc < 8; cc++) { wv[cc] = wr4[cc]; xv[cc] = xc4[cc]; }
    }

    if (tid < 10) {
        float crx = cosf(th_rx0[tid] * 0.5f), srx = sinf(th_rx0[tid] * 0.5f);
        float cry = cosf(th_ry0[tid] * 0.5f), sry = sinf(th_ry0[tid] * 0.5f);
        M1w[tid][0][0] = make_float2( cry * crx,  sry * srx);
        M1w[tid][0][1] = make_float2(-sry * crx, -cry * srx);
        M1w[tid][1][0] = make_float2( sry * crx, -cry * srx);
        M1w[tid][1][1] = make_float2( cry * crx, -sry * srx);
        float c1 = cosf(th_ry1[tid] * 0.5f), s1 = sinf(th_ry1[tid] * 0.5f);
        M2w[tid][0][0] =  c1; M2w[tid][0][1] = -s1;
        M2w[tid][1][0] =  s1; M2w[tid][1][1] =  c1;
    }
    __syncthreads();

    // Kronecker factors (2 cells per thread)
    for (int cell = tid; cell < 1024; cell += 512) {
        int r = cell >> 5, c = cell & 31;
        float2 ga = make_float2(1.f, 0.f), gb = make_float2(1.f, 0.f);
        float g2a = 1.f, g2b = 1.f;
#pragma unroll
        for (int j = 0; j < 5; j++) {
            int rb = (r >> (4 - j)) & 1;
            int cb = (c >> (4 - j)) & 1;
            ga  = cmul(ga, M1w[j][rb][cb]);
            gb  = cmul(gb, M1w[5 + j][rb][cb]);
            g2a *= M2w[j][rb][cb];
            g2b *= M2w[5 + j][rb][cb];
        }
        Ga[r][c] = ga; Gb[r][c] = gb; G2a[r][c] = g2a; G2b[r][c] = g2b;
    }

    // Consume GEMV loads
    {
        float s = 0.f;
#pragma unroll
        for (int cc = 0; cc < 8; cc++)
            s += wv[cc].x * xv[cc].x + wv[cc].y * xv[cc].y +
                 wv[cc].z * xv[cc].z + wv[cc].w * xv[cc].w;
        partial[gp][gk] = s;
    }
    __syncthreads();

    if (tid < 32) {
        float v = bias[tid];
#pragma unroll
        for (int p = 0; p < 16; p++) v += partial[p][tid];
        float sq = v * v;
#pragma unroll
        for (int o = 16; o; o >>= 1) sq += __shfl_xor_sync(0xffffffffu, sq, o);
        e[tid] = v * rsqrtf(sq);
    }
    __syncthreads();

    // u = Ga * e, v = Gb * e
    if (tid < 64) {
        int r = tid & 31, side = tid >> 5;
        float re = 0.f, im = 0.f;
#pragma unroll
        for (int c = 0; c < 32; c++) {
            float ev = e[c];
            float2 m = side ? Gb[r][c] : Ga[r][c];
            re += m.x * ev; im += m.y * ev;
        }
        if (side) vs[r] = make_float2(re, im);
        else      us[r] = make_float2(re, im);
    }
    __syncthreads();

    // P/Q: 256 complex outputs, threads 0..255
    if (tid < 256) {
        int which = tid >> 7;           // 0 -> P, 1 -> Q
        int k4 = (tid >> 5) & 3;
        int rr = tid & 31;
        float re = 0.f, im = 0.f;
        if (which == 0) {
            int pa = k4 >> 1, fa = (k4 & 1) << 4;
#pragma unroll
            for (int mm = 0; mm < 16; mm++) {
                int m = (mm << 1) | pa;
                float2 uu = us[m ^ (m >> 1)];
                float g = G2a[rr][m ^ fa];
                re += g * uu.x; im += g * uu.y;
            }
            d_Pxx[tok][k4][rr] = make_float2(re, re);
            d_Pyn[tok][k4][rr] = make_float2(-im, -im);
            d_P[tok][k4][rr]   = make_float2(re, im);
        } else {
            int pb = k4 & 1, xb = (k4 >> 1) << 4;
#pragma unroll
            for (int mm = 0; mm < 16; mm++) {
                int m = (mm << 1) | pb;
                float2 vv = vs[(m ^ (m >> 1)) ^ xb];
                float g = G2b[rr][m];
                re += g * vv.x; im += g * vv.y;
            }
            d_Qx[tok][k4][rr] = re;
            d_Qy[tok][k4][rr] = im;
            d_Q[tok][k4][rr]  = make_float2(re, im);
        }
    }
}

// ---------------------------------------------------------------------------
// Kernel 2: rank-4 expansion, REAL parts. grid = 128 (block per token (b,i)),
// block = 512 = 8 j-lanes x 64 patch threads; 4 j-iterations.
// Q of batch b staged once into smem SoA; P loaded pre-packed from global.
// Per j: 8 LDS.128 + 32 fma.rn.f32x2 + 4 STG.128 per thread.
//   out[(tok*32 + j)*1024 + a*32 + b0] = sum_k Px*Qx - Py*Qy
// ---------------------------------------------------------------------------
__global__ void __launch_bounds__(512)
expand_real_kernel(float* __restrict__ out) {
    __shared__ float Qx[32][4][32];   // [j][k][b0]
    __shared__ float Qy[32][4][32];

    int tok = blockIdx.x;          // b*32 + i
    int b = tok >> 5;
    int t = threadIdx.x;           // 512

    // Stage all Q of batch b (SoA): 4096 floats each array = 1024 float4
    {
        const float4* gx = (const float4*)&d_Qx[b << 5][0][0];
        const float4* gy = (const float4*)&d_Qy[b << 5][0][0];
        float4* sx = (float4*)&Qx[0][0][0];
        float4* sy = (float4*)&Qy[0][0][0];
#pragma unroll
        for (int n = 0; n < 2; n++) {
            int idx = t + n * 512;
            sx[idx] = gx[idx];
            sy[idx] = gy[idx];
        }
    }

    int lane = t >> 6;             // 0..7 (j-lane)
    int t4 = t & 63;
    int a_base = (t4 >> 3) << 2;   // 0,4,...,28
    int b0 = (t4 & 7) << 2;        // 0,4,...,28

    // P: pre-packed (Px,Px) / (-Py,-Py) pairs for this block's token
    unsigned long long pxx[4][4], pyn[4][4];
#pragma unroll
    for (int k = 0; k < 4; k++) {
        const ulonglong2* px = (const ulonglong2*)&d_Pxx[tok][k][a_base];
        ulonglong2 v0 = px[0], v1 = px[1];
        pxx[0][k] = v0.x; pxx[1][k] = v0.y; pxx[2][k] = v1.x; pxx[3][k] = v1.y;
        const ulonglong2* py = (const ulonglong2*)&d_Pyn[tok][k][a_base];
        ulonglong2 w0 = py[0], w1 = py[1];
        pyn[0][k] = w0.x; pyn[1][k] = w0.y; pyn[2][k] = w1.x; pyn[3][k] = w1.y;
    }
    __syncthreads();

    float* obase = out + ((size_t)tok << 15);   // tok*32*1024
#pragma unroll
    for (int jo = 0; jo < 4; jo++) {
        int j = (jo << 3) | lane;
        unsigned long long qxL[4], qxH[4], qyL[4], qyH[4];
#pragma unroll
        for (int k = 0; k < 4; k++) {
            float4 fx = *(const float4*)&Qx[j][k][b0];
            qxL[k] = pack2(fx.x, fx.y); qxH[k] = pack2(fx.z, fx.w);
            float4 fy = *(const float4*)&Qy[j][k][b0];
            qyL[k] = pack2(fy.x, fy.y); qyH[k] = pack2(fy.z, fy.w);
        }
        float* oj = obase + ((size_t)j << 10);
#pragma unroll
        for (int da = 0; da < 4; da++) {
            unsigned long long accL = 0ull, accH = 0ull;   // (0.0f,0.0f)
#pragma unroll
            for (int k = 0; k < 4; k++) {
                accL = fma2(pxx[da][k], qxL[k], accL);
                accL = fma2(pyn[da][k], qyL[k], accL);
                accH = fma2(pxx[da][k], qxH[k], accH);
                accH = fma2(pyn[da][k], qyH[k], accH);
            }
            float r0, r1, r2, r3;
            unpack2(accL, r0, r1);
            unpack2(accH, r2, r3);
            *(float4*)&oj[(a_base + da) * 32 + b0] = make_float4(r0, r1, r2, r3);
        }
    }
}

// ---------------------------------------------------------------------------
// Fallback (out_size != 4194304): interleaved complex pairs.
// ---------------------------------------------------------------------------
__global__ void __launch_bounds__(512)
expand_cplx_kernel(float4* __restrict__ out, long long nf4_limit) {
    int blk = blockIdx.x;          // b*1024 + i*32 + j
    int b = blk >> 10;
    int i = (blk >> 5) & 31;
    int j = blk & 31;

    __shared__ float2 Ps[4][32];
    __shared__ float2 Qs[4][32];

    int tid = threadIdx.x;  // 512
    if (tid < 128) {
        Ps[tid >> 5][tid & 31] = d_P[b * T + i][tid >> 5][tid & 31];
    } else if (tid < 256) {
        int t = tid - 128;
        Qs[t >> 5][t & 31] = d_Q[b * T + j][t >> 5][t & 31];
    }
    __syncthreads();

    int e0 = tid * 2;
    int a  = e0 >> 5;
    int b0 = e0 & 31;

    unsigned long long acc0 = 0ull, acc1 = 0ull;
#pragma unroll
    for (int k = 0; k < 4; k++) {
        float2 P  = Ps[k][a];
        float2 Q0 = Qs[k][b0];
        float2 Q1 = Qs[k][b0 + 1];
        unsigned long long pxx = pack2(P.x, P.x);
        unsigned long long pyn = pack2(-P.y, P.y);
        acc0 = fma2(pxx, pack2(Q0.x, Q0.y), acc0);
        acc0 = fma2(pyn, pack2(Q0.y, Q0.x), acc0);
        acc1 = fma2(pxx, pack2(Q1.x, Q1.y), acc1);
        acc1 = fma2(pyn, pack2(Q1.y, Q1.x), acc1);
    }
    float re0, im0, re1, im1;
    unpack2(acc0, re0, im0);
    unpack2(acc1, re1, im1);

    long long idx = (long long)blk * 512 + tid;
    if (idx < nf4_limit)
        out[idx] = make_float4(re0, im0, re1, im1);
}

// ---------------------------------------------------------------------------
extern "C" void kernel_launch(void* const* d_in, const int* in_sizes, int n_in,
                              void* d_out, int out_size) {
    // Resolve inputs by element count (order-independent):
    //   x: 65536 (B*T*C), W_tok: 16384 (ENC*C), b_tok: 32 (ENC),
    //   thetas: three size-10 arrays, relative order rx0, ry0, ry1.
    const float* x = nullptr;
    const float* W = nullptr;
    const float* bvec = nullptr;
    const float* th[3] = {nullptr, nullptr, nullptr};
    int nth = 0;
    for (int i = 0; i < n_in; i++) {
        int sz = in_sizes[i];
        const float* p = (const float*)d_in[i];
        if (sz == BATCH * T * C)      x = p;
        else if (sz == ENC * C)       W = p;
        else if (sz == ENC)           bvec = p;
        else if (sz == 10 && nth < 3) th[nth++] = p;
    }
    if (!x || !W || !bvec || nth != 3) return;

    enc_pq_kernel<<<NTOK, 512>>>(x, W, bvec, th[0], th[1], th[2]);

    if (out_size == 4194304) {
        // Live path: float32 output, 4M elements (16MB): real parts only.
        expand_real_kernel<<<NTOK, 512>>>((float*)d_out);
    } else {
        // Fallback: interleaved complex pairs.
        long long nfloats = (long long)out_size;
        if (nfloats > 8388608LL) nfloats = 8388608LL;
        long long nf4 = nfloats / 4;
        if (nf4 > 2097152LL) nf4 = 2097152LL;
        expand_cplx_kernel<<<BATCH * T * T, 512>>>((float4*)d_out, nf4);
    }
}